// round 11
// baseline (speedup 1.0000x reference)
#include <cuda_runtime.h>
#include <cuda_bf16.h>
#include <mma.h>
#include <math.h>
#include <cstdint>
#include <stdint.h>

using namespace nvcuda;

// Problem constants
#define Lc 15
#define Dc 512
#define Hc 64
#define HDc 8
#define Fc 2048
#define Gc 128
#define Bc 4
#define Nc 256
#define Mc (Bc*Nc)   // 1024 rows
#define SPLITK 4
#define TABN 8192

// Weight split-region bases (elements) inside g_wh/g_wl
#define QKVB 0
#define OUTB 11796480
#define F1B  15728640
#define F2B  31457280
#define WTOT 47185920

// -------- scratch (device globals; no allocation allowed) --------
__device__ float g_h[Mc*Dc];
__device__ float g_qkv[Mc*3*Dc];
__device__ float g_pair[Bc*Nc*Nc];
__device__ float g_split[SPLITK*Mc*Dc];
__device__ float g_tab[TABN+1];
__device__ __nv_bfloat16 g_xh[Mc*Dc],  g_xl[Mc*Dc];
__device__ __nv_bfloat16 g_ah[Mc*Dc],  g_al[Mc*Dc];
__device__ __nv_bfloat16 g_fh[Mc*Fc],  g_fl[Mc*Fc];
__device__ __nv_bfloat16 g_wh[WTOT],   g_wl[WTOT];

// ---------------- gaussian table build ----------------
__global__ void tab_kernel(const float* __restrict__ mu,
                           const float* __restrict__ sigma,
                           const float* __restrict__ plw,
                           const float* __restrict__ plb) {
    int i = blockIdx.x*256 + threadIdx.x;
    if (i > TABN) return;
    float da = -8.0f + (float)i * (1.0f/512.0f);
    float s = 0.f;
    #pragma unroll 8
    for (int g = 0; g < Gc; g++) {
        float sg = sigma[g];
        float coef = plw[g] / (2.0f*sg*sg) / (sg * 2.5066282746310002f);
        float t = da - mu[g];
        s += __expf(-t*t) * coef;
    }
    g_tab[i] = s + plb[0];
}

// ---------------- pair representation via table lookup ----------------
__global__ void pair_kernel(const float* __restrict__ coords,
                            const int* __restrict__ ptypes,
                            const float* __restrict__ pa,
                            const float* __restrict__ pb,
                            float* __restrict__ pr) {
    int p = blockIdx.x * blockDim.x + threadIdx.x;
    int b = p >> 16;
    int rem = p & 65535;
    int i = rem >> 8, j = rem & 255;
    const float* ci = coords + (b*Nc + i)*3;
    const float* cj = coords + (b*Nc + j)*3;
    float dx = ci[0]-cj[0], dy = ci[1]-cj[1], dz = ci[2]-cj[2];
    float d2 = dx*dx + dy*dy + dz*dz;
    float dist = sqrtf(fmaxf(d2, 1e-12f));
    int pt = ptypes[p];
    float da = pa[pt]*dist + pb[pt];
    float t = (da + 8.0f) * 512.0f;
    t = fminf(fmaxf(t, 0.0f), (float)(TABN - 1));
    int idx = (int)t;
    float fr = t - (float)idx;
    float f0 = g_tab[idx], f1 = g_tab[idx+1];
    pr[p] = f0 + fr*(f1 - f0);
}

// ---------------- weight split: fp32 -> bf16 hi/lo ----------------
__global__ void wsplit_kernel(const float* __restrict__ src,
                              __nv_bfloat16* __restrict__ dh,
                              __nv_bfloat16* __restrict__ dl, int n4) {
    int i = blockIdx.x*256 + threadIdx.x;
    if (i >= n4) return;
    float4 v = ((const float4*)src)[i];
    __nv_bfloat16 h0 = __float2bfloat16(v.x), h1 = __float2bfloat16(v.y);
    __nv_bfloat16 h2 = __float2bfloat16(v.z), h3 = __float2bfloat16(v.w);
    __nv_bfloat16 l0 = __float2bfloat16(v.x - __bfloat162float(h0));
    __nv_bfloat16 l1 = __float2bfloat16(v.y - __bfloat162float(h1));
    __nv_bfloat16 l2 = __float2bfloat16(v.z - __bfloat162float(h2));
    __nv_bfloat16 l3 = __float2bfloat16(v.w - __bfloat162float(h3));
    ((__nv_bfloat162*)dh)[i*2]   = __halves2bfloat162(h0, h1);
    ((__nv_bfloat162*)dh)[i*2+1] = __halves2bfloat162(h2, h3);
    ((__nv_bfloat162*)dl)[i*2]   = __halves2bfloat162(l0, l1);
    ((__nv_bfloat162*)dl)[i*2+1] = __halves2bfloat162(l2, l3);
}

// ---------------- embedding ----------------
__global__ void emb_kernel(const int* __restrict__ atom_types,
                           const float* __restrict__ atom_emb,
                           float* __restrict__ h) {
    int idx = blockIdx.x * blockDim.x + threadIdx.x;
    if (idx >= Mc*Dc) return;
    int row = idx >> 9;
    int d   = idx & 511;
    h[idx] = atom_emb[atom_types[row]*Dc + d];
}

// ---------------- layernorm (emits split bf16) ----------------
__global__ __launch_bounds__(128) void ln_kernel(const float* __restrict__ in,
                                                 const float* __restrict__ g,
                                                 const float* __restrict__ bb,
                                                 __nv_bfloat16* __restrict__ xh,
                                                 __nv_bfloat16* __restrict__ xl) {
    int row = blockIdx.x;
    int tid = threadIdx.x;
    const float* x = in + row*Dc;
    float v[4], s = 0.f, s2 = 0.f;
    #pragma unroll
    for (int j = 0; j < 4; j++) {
        v[j] = x[tid + 128*j];
        s += v[j]; s2 += v[j]*v[j];
    }
    #pragma unroll
    for (int off = 16; off; off >>= 1) {
        s  += __shfl_xor_sync(0xffffffff, s,  off);
        s2 += __shfl_xor_sync(0xffffffff, s2, off);
    }
    __shared__ float rs[4], rs2[4];
    int wid = tid >> 5, lane = tid & 31;
    if (lane == 0) { rs[wid] = s; rs2[wid] = s2; }
    __syncthreads();
    s  = rs[0]+rs[1]+rs[2]+rs[3];
    s2 = rs2[0]+rs2[1]+rs2[2]+rs2[3];
    float mean = s * (1.0f/Dc);
    float var  = s2 * (1.0f/Dc) - mean*mean;
    float rstd = rsqrtf(var + 1e-5f);
    #pragma unroll
    for (int j = 0; j < 4; j++) {
        int d = tid + 128*j;
        float y = (v[j]-mean)*rstd*g[d] + bb[d];
        __nv_bfloat16 hi = __float2bfloat16(y);
        xh[row*Dc + d] = hi;
        xl[row*Dc + d] = __float2bfloat16(y - __bfloat162float(hi));
    }
}

// ---------------- fused split-K reduce + layernorm (emits split bf16) ----------------
__global__ __launch_bounds__(128) void reduce_ln_kernel(
    const float* __restrict__ P, const float* __restrict__ bias,
    float* __restrict__ h, const float* __restrict__ g,
    const float* __restrict__ bb,
    __nv_bfloat16* __restrict__ xh, __nv_bfloat16* __restrict__ xl) {
    int row = blockIdx.x;
    int tid = threadIdx.x;
    const int MN = Mc*Dc;
    float v[4], s = 0.f, s2 = 0.f;
    #pragma unroll
    for (int j = 0; j < 4; j++) {
        int d = tid + 128*j;
        int idx = row*Dc + d;
        float val = h[idx] + bias[d]
                  + P[idx] + P[idx + MN] + P[idx + 2*MN] + P[idx + 3*MN];
        h[idx] = val;
        v[j] = val; s += val; s2 += val*val;
    }
    #pragma unroll
    for (int off = 16; off; off >>= 1) {
        s  += __shfl_xor_sync(0xffffffff, s,  off);
        s2 += __shfl_xor_sync(0xffffffff, s2, off);
    }
    __shared__ float rs[4], rs2[4];
    int wid = tid >> 5, lane = tid & 31;
    if (lane == 0) { rs[wid] = s; rs2[wid] = s2; }
    __syncthreads();
    s  = rs[0]+rs[1]+rs[2]+rs[3];
    s2 = rs2[0]+rs2[1]+rs2[2]+rs2[3];
    float mean = s * (1.0f/Dc);
    float var  = s2 * (1.0f/Dc) - mean*mean;
    float rstd = rsqrtf(var + 1e-5f);
    #pragma unroll
    for (int j = 0; j < 4; j++) {
        int d = tid + 128*j;
        float y = (v[j]-mean)*rstd*g[d] + bb[d];
        __nv_bfloat16 hi = __float2bfloat16(y);
        xh[row*Dc + d] = hi;
        xl[row*Dc + d] = __float2bfloat16(y - __bfloat162float(hi));
    }
}

// ---------------- plain split-K reduce (final layer) ----------------
__global__ __launch_bounds__(256) void reduce_splitk(const float* __restrict__ P,
                                                     const float* __restrict__ bias,
                                                     float* __restrict__ h,
                                                     int MN, int N) {
    int i4 = blockIdx.x*256 + threadIdx.x;
    if (i4 >= MN/4) return;
    int n = (i4*4) & (N-1);
    const float4* P4 = (const float4*)P;
    int stride4 = MN/4;
    float4 s0 = P4[i4];
    float4 s1 = P4[i4 + stride4];
    float4 s2 = P4[i4 + 2*stride4];
    float4 s3 = P4[i4 + 3*stride4];
    float4 b  = *(const float4*)(bias + n);
    float4 hv = ((float4*)h)[i4];
    hv.x += s0.x + s1.x + s2.x + s3.x + b.x;
    hv.y += s0.y + s1.y + s2.y + s3.y + b.y;
    hv.z += s0.z + s1.z + s2.z + s3.z + b.z;
    hv.w += s0.w + s1.w + s2.w + s3.w + b.w;
    ((float4*)h)[i4] = hv;
}

// ---------------- bf16x3 GEMM, pre-split operands, LDG->STS pipeline ----------------
// D = Ah*Wh^T + Ah*Wl^T + Al*Wh^T  (fp32 acc)
// direct (bias==null && oh==null): raw fp32 frag stores to C (+z*M*N if split-K)
// staged: +bias [,gelu]; oh/ol -> split bf16 out
#define BM 128
#define BN 64
#define BKT 32
#define LDA 40
#define LDC 68
#define SBUF 30720          // (128+128+64+64) rows * 40 bf16 * 2B
#define SMEM_DYN (2*SBUF)
__global__ __launch_bounds__(256, 2) void gemm_tc_kernel(
    const __nv_bfloat16* __restrict__ Ahg, const __nv_bfloat16* __restrict__ Alg,
    const __nv_bfloat16* __restrict__ Whg, const __nv_bfloat16* __restrict__ Wlg,
    const float* __restrict__ bias,
    float* __restrict__ C,
    __nv_bfloat16* __restrict__ oh, __nv_bfloat16* __restrict__ ol,
    int M, int N, int K, int act)
{
    extern __shared__ __align__(16) char smem[];
    int tid = threadIdx.x;
    int m0 = blockIdx.y*BM, n0 = blockIdx.x*BN;
    int S = gridDim.z;
    int Ks = K / S;
    int kbeg = blockIdx.z * Ks;

    int wid = tid >> 5;
    int wm = (wid >> 1) * 32;
    int wn = (wid & 1) * 32;

    // chunk mapping: row = tid>>2 (0..63), c = (tid&3)*8 (k offset in bf16)
    int arow = tid >> 2, ac = (tid & 3) * 8;
    const __nv_bfloat16* pAh0 = Ahg + (size_t)(m0+arow)*K + kbeg + ac;
    const __nv_bfloat16* pAh1 = pAh0 + (size_t)64*K;
    const __nv_bfloat16* pAl0 = Alg + (size_t)(m0+arow)*K + kbeg + ac;
    const __nv_bfloat16* pAl1 = pAl0 + (size_t)64*K;
    const __nv_bfloat16* pWh  = Whg + (size_t)(n0+arow)*K + kbeg + ac;
    const __nv_bfloat16* pWl  = Wlg + (size_t)(n0+arow)*K + kbeg + ac;
    unsigned offA = (unsigned)(arow*LDA + ac);   // element offset (16B-aligned bytes)

    wmma::fragment<wmma::accumulator, 16, 16, 16, float> acc[2][2];
    #pragma unroll
    for (int i = 0; i < 2; i++)
        #pragma unroll
        for (int j = 0; j < 2; j++)
            wmma::fill_fragment(acc[i][j], 0.0f);

    // prefetch tile 0
    uint4 ra0 = *(const uint4*)pAh0;
    uint4 ra1 = *(const uint4*)pAh1;
    uint4 rl0 = *(const uint4*)pAl0;
    uint4 rl1 = *(const uint4*)pAl1;
    uint4 rw0 = *(const uint4*)pWh;
    uint4 rw1 = *(const uint4*)pWl;

    int nt = Ks / BKT;
    for (int t = 0; t < nt; t++) {
        char* buf = smem + (t & 1)*SBUF;
        __nv_bfloat16* Ah = (__nv_bfloat16*)buf;
        __nv_bfloat16* Al = Ah + BM*LDA;
        __nv_bfloat16* Wh = Al + BM*LDA;
        __nv_bfloat16* Wl = Wh + BN*LDA;

        *(uint4*)&Ah[offA]          = ra0;
        *(uint4*)&Ah[offA + 64*LDA] = ra1;
        *(uint4*)&Al[offA]          = rl0;
        *(uint4*)&Al[offA + 64*LDA] = rl1;
        *(uint4*)&Wh[offA]          = rw0;
        *(uint4*)&Wl[offA]          = rw1;

        if (t + 1 < nt) {
            int k0 = (t+1)*BKT;
            ra0 = *(const uint4*)(pAh0 + k0);
            ra1 = *(const uint4*)(pAh1 + k0);
            rl0 = *(const uint4*)(pAl0 + k0);
            rl1 = *(const uint4*)(pAl1 + k0);
            rw0 = *(const uint4*)(pWh + k0);
            rw1 = *(const uint4*)(pWl + k0);
        }

        __syncthreads();   // the ONLY barrier per tile

        #pragma unroll
        for (int ks = 0; ks < BKT; ks += 16) {
            wmma::fragment<wmma::matrix_a, 16, 16, 16, __nv_bfloat16, wmma::row_major> ah[2], al[2];
            #pragma unroll
            for (int i = 0; i < 2; i++) {
                wmma::load_matrix_sync(ah[i], Ah + (wm + i*16)*LDA + ks, LDA);
                wmma::load_matrix_sync(al[i], Al + (wm + i*16)*LDA + ks, LDA);
            }
            #pragma unroll
            for (int j = 0; j < 2; j++) {
                wmma::fragment<wmma::matrix_b, 16, 16, 16, __nv_bfloat16, wmma::col_major> bh, bl;
                wmma::load_matrix_sync(bh, Wh + (wn + j*16)*LDA + ks, LDA);
                wmma::load_matrix_sync(bl, Wl + (wn + j*16)*LDA + ks, LDA);
                #pragma unroll
                for (int i = 0; i < 2; i++) {
                    wmma::mma_sync(acc[i][j], ah[i], bh, acc[i][j]);
                    wmma::mma_sync(acc[i][j], ah[i], bl, acc[i][j]);
                    wmma::mma_sync(acc[i][j], al[i], bh, acc[i][j]);
                }
            }
        }
        // no trailing sync: next iter writes the other buffer.
    }

    if (bias == nullptr && oh == nullptr) {
        // direct frag stores (QKV raw, split-K partials)
        float* Cp = C + (size_t)blockIdx.z*M*N;
        #pragma unroll
        for (int i = 0; i < 2; i++)
            #pragma unroll
            for (int j = 0; j < 2; j++)
                wmma::store_matrix_sync(Cp + (size_t)(m0+wm+i*16)*N + n0+wn+j*16,
                                        acc[i][j], N, wmma::mem_row_major);
        return;
    }

    __syncthreads();   // before aliasing smem as epilogue tile
    float* Ct = (float*)smem;
    #pragma unroll
    for (int i = 0; i < 2; i++)
        #pragma unroll
        for (int j = 0; j < 2; j++)
            wmma::store_matrix_sync(Ct + (wm+i*16)*LDC + wn+j*16,
                                    acc[i][j], LDC, wmma::mem_row_major);
    __syncthreads();

    int col = (tid & 15) * 4;
    int r0  = tid >> 4;
    float4 bv = *(const float4*)(bias + n0 + col);
    #pragma unroll
    for (int rr = 0; rr < 8; rr++) {
        int row = rr*16 + r0;
        float vr[4];
        *(float4*)vr = *(const float4*)&Ct[row*LDC + col];
        vr[0] += bv.x; vr[1] += bv.y; vr[2] += bv.z; vr[3] += bv.w;
        if (act == 1) {
            #pragma unroll
            for (int j = 0; j < 4; j++)
                vr[j] = 0.5f * vr[j] * (1.0f + erff(vr[j] * 0.7071067811865475f));
        }
        size_t base = (size_t)(m0+row)*N + n0 + col;
        if (oh) {
            __nv_bfloat16 h0 = __float2bfloat16(vr[0]), h1 = __float2bfloat16(vr[1]);
            __nv_bfloat16 h2 = __float2bfloat16(vr[2]), h3 = __float2bfloat16(vr[3]);
            __nv_bfloat16 l0 = __float2bfloat16(vr[0] - __bfloat162float(h0));
            __nv_bfloat16 l1 = __float2bfloat16(vr[1] - __bfloat162float(h1));
            __nv_bfloat16 l2 = __float2bfloat16(vr[2] - __bfloat162float(h2));
            __nv_bfloat16 l3 = __float2bfloat16(vr[3] - __bfloat162float(h3));
            *(__nv_bfloat162*)&oh[base]   = __halves2bfloat162(h0, h1);
            *(__nv_bfloat162*)&oh[base+2] = __halves2bfloat162(h2, h3);
            *(__nv_bfloat162*)&ol[base]   = __halves2bfloat162(l0, l1);
            *(__nv_bfloat162*)&ol[base+2] = __halves2bfloat162(l2, l3);
        } else {
            *(float4*)(C + base) = *(float4*)vr;
        }
    }
}

// ---------------- fused attention (QKV bias + scores + softmax + PV) ----------------
// outputs split bf16 (oh/ol) for the out-proj GEMM
__global__ __launch_bounds__(256) void attn_kernel(const float* __restrict__ qkv,
                                                   const float* __restrict__ qb,
                                                   const float* __restrict__ pr,
                                                   const float* __restrict__ ppw,
                                                   const float* __restrict__ ppb,
                                                   __nv_bfloat16* __restrict__ oh,
                                                   __nv_bfloat16* __restrict__ ol) {
    int b = blockIdx.x >> 6;
    int h = blockIdx.x & 63;
    __shared__ float Ks[Nc*9];
    __shared__ float Vs[Nc*9];
    int tid = threadIdx.x;
    float4 bq0 = *(const float4*)(qb + h*HDc);
    float4 bq1 = *(const float4*)(qb + h*HDc + 4);
    float4 bk0 = *(const float4*)(qb + Dc + h*HDc);
    float4 bk1 = *(const float4*)(qb + Dc + h*HDc + 4);
    float4 bv0 = *(const float4*)(qb + 2*Dc + h*HDc);
    float4 bv1 = *(const float4*)(qb + 2*Dc + h*HDc + 4);
    {
        int n = tid;
        const float* kp = qkv + (((b*Nc + n)*3 + 1))*Dc + h*HDc;
        const float* vp = kp + Dc;
        float4 k0 = *(const float4*)kp,     k1 = *(const float4*)(kp+4);
        float4 v0 = *(const float4*)vp,     v1 = *(const float4*)(vp+4);
        float* kd = &Ks[n*9];
        kd[0]=k0.x+bk0.x; kd[1]=k0.y+bk0.y; kd[2]=k0.z+bk0.z; kd[3]=k0.w+bk0.w;
        kd[4]=k1.x+bk1.x; kd[5]=k1.y+bk1.y; kd[6]=k1.z+bk1.z; kd[7]=k1.w+bk1.w;
        float* vd = &Vs[n*9];
        vd[0]=v0.x+bv0.x; vd[1]=v0.y+bv0.y; vd[2]=v0.z+bv0.z; vd[3]=v0.w+bv0.w;
        vd[4]=v1.x+bv1.x; vd[5]=v1.y+bv1.y; vd[6]=v1.z+bv1.z; vd[7]=v1.w+bv1.w;
    }
    __syncthreads();
    const float scale = 0.3535533905932738f;
    float pw = ppw[h], pb = ppb[h];
    int warp = tid >> 5, lane = tid & 31;
    #pragma unroll
    for (int r = 0; r < 8; r++) {
        int i = blockIdx.y*64 + warp*8 + r;
        const float* qp = qkv + ((b*Nc + i)*3)*Dc + h*HDc;
        float4 q0 = *(const float4*)qp, q1 = *(const float4*)(qp+4);
        float qr[8];
        qr[0]=q0.x+bq0.x; qr[1]=q0.y+bq0.y; qr[2]=q0.z+bq0.z; qr[3]=q0.w+bq0.w;
        qr[4]=q1.x+bq1.x; qr[5]=q1.y+bq1.y; qr[6]=q1.z+bq1.z; qr[7]=q1.w+bq1.w;
        const float* prow = pr + (b*Nc + i)*Nc;
        float s[8];
        float mx = -1e30f;
        #pragma unroll
        for (int jj = 0; jj < 8; jj++) {
            int j = lane + 32*jj;
            const float* kk = &Ks[j*9];
            float d = qr[0]*kk[0] + qr[1]*kk[1] + qr[2]*kk[2] + qr[3]*kk[3]
                    + qr[4]*kk[4] + qr[5]*kk[5] + qr[6]*kk[6] + qr[7]*kk[7];
            s[jj] = d*scale + prow[j]*pw + pb;
            mx = fmaxf(mx, s[jj]);
        }
        #pragma unroll
        for (int off = 16; off; off >>= 1)
            mx = fmaxf(mx, __shfl_xor_sync(0xffffffff, mx, off));
        float sum = 0.f;
        #pragma unroll
        for (int jj = 0; jj < 8; jj++) { s[jj] = __expf(s[jj]-mx); sum += s[jj]; }
        #pragma unroll
        for (int off = 16; off; off >>= 1)
            sum += __shfl_xor_sync(0xffffffff, sum, off);
        float inv = 1.0f / sum;
        float acc[8] = {};
        #pragma unroll
        for (int jj = 0; jj < 8; jj++) {
            int j = lane + 32*jj;
            float p = s[jj]*inv;
            const float* vv = &Vs[j*9];
            #pragma unroll
            for (int d = 0; d < 8; d++) acc[d] += p*vv[d];
        }
        #pragma unroll
        for (int off = 16; off; off >>= 1) {
            #pragma unroll
            for (int d = 0; d < 8; d++)
                acc[d] += __shfl_xor_sync(0xffffffff, acc[d], off);
        }
        if (lane == 0) {
            size_t base = (size_t)(b*Nc + i)*Dc + h*HDc;
            #pragma unroll
            for (int d = 0; d < 8; d++) {
                __nv_bfloat16 hi = __float2bfloat16(acc[d]);
                oh[base + d] = hi;
                ol[base + d] = __float2bfloat16(acc[d] - __bfloat162float(hi));
            }
        }
    }
}

// ---------------- SE(3) coordinate update ----------------
__global__ __launch_bounds__(128) void coords_kernel(const float* __restrict__ coords,
                                                     const float* __restrict__ pr,
                                                     const float* __restrict__ uw,
                                                     const float* __restrict__ ub,
                                                     const float* __restrict__ ww,
                                                     const float* __restrict__ wb,
                                                     float* __restrict__ out) {
    int gw = blockIdx.x * 4 + (threadIdx.x >> 5);
    int lane = threadIdx.x & 31;
    int b = gw >> 8, i = gw & 255;
    float u0 = uw[0], u1 = ub[0], w0 = ww[0], w1 = wb[0];
    const float* ci = coords + (b*Nc + i)*3;
    float cx = ci[0], cy = ci[1], cz = ci[2];
    float ax = 0.f, ay = 0.f, az = 0.f;
    const float* prow = pr + (b*Nc + i)*Nc;
    #pragma unroll
    for (int jj = 0; jj < 8; jj++) {
        int j = lane + 32*jj;
        const float* cj = coords + (b*Nc + j)*3;
        float c = (fmaxf(prow[j], 0.f)*u0 + u1)*w0 + w1;
        ax += (cx - cj[0])*c;
        ay += (cy - cj[1])*c;
        az += (cz - cj[2])*c;
    }
    #pragma unroll
    for (int off = 16; off; off >>= 1) {
        ax += __shfl_xor_sync(0xffffffff, ax, off);
        ay += __shfl_xor_sync(0xffffffff, ay, off);
        az += __shfl_xor_sync(0xffffffff, az, off);
    }
    if (lane == 0) {
        float invn = 1.0f / (256.0f + 1e-6f);
        float* op = out + (b*Nc + i)*3;
        op[0] = cx + ax*invn;
        op[1] = cy + ay*invn;
        op[2] = cz + az*invn;
    }
}

// ---------------- energy head ----------------
__global__ __launch_bounds__(128) void energy_kernel(const float* __restrict__ h,
                                                     const float* __restrict__ enw,
                                                     const float* __restrict__ enb,
                                                     float* __restrict__ out) {
    int b = blockIdx.x;
    int tid = threadIdx.x;
    const float* row = h + (b*Nc)*Dc;
    float s = 0.f;
    #pragma unroll
    for (int j = 0; j < 4; j++) {
        int d = tid + 128*j;
        s += row[d]*enw[d];
    }
    #pragma unroll
    for (int off = 16; off; off >>= 1)
        s += __shfl_xor_sync(0xffffffff, s, off);
    __shared__ float rs[4];
    int wid = tid >> 5, lane = tid & 31;
    if (lane == 0) rs[wid] = s;
    __syncthreads();
    if (tid == 0)
        out[Bc*Nc*3 + b] = rs[0]+rs[1]+rs[2]+rs[3] + enb[0];
}

// ---------------- host ----------------
extern "C" void kernel_launch(void* const* d_in, const int* in_sizes, int n_in,
                              void* d_out, int out_size) {
    bool has_mask = (n_in >= 31);
    auto IN = [&](int i) -> const void* {
        int k = i;
        if (!has_mask && i > 3) k = i - 1;
        return d_in[k];
    };
    const int*   atom_types = (const int*)  IN(0);
    const float* coords     = (const float*)IN(1);
    const int*   pair_types = (const int*)  IN(2);
    const float* atom_emb   = (const float*)IN(4);
    const float* gmu        = (const float*)IN(5);
    const float* gsigma     = (const float*)IN(6);
    const float* pair_a     = (const float*)IN(7);
    const float* pair_b     = (const float*)IN(8);
    const float* pl_w       = (const float*)IN(9);
    const float* pl_b       = (const float*)IN(10);
    const float* ln1_g      = (const float*)IN(11);
    const float* ln1_b      = (const float*)IN(12);
    const float* qkv_w      = (const float*)IN(13);
    const float* qkv_b      = (const float*)IN(14);
    const float* pp_w       = (const float*)IN(15);
    const float* pp_b       = (const float*)IN(16);
    const float* out_w      = (const float*)IN(17);
    const float* out_b      = (const float*)IN(18);
    const float* ln2_g      = (const float*)IN(19);
    const float* ln2_b      = (const float*)IN(20);
    const float* ffn_w1     = (const float*)IN(21);
    const float* ffn_b1     = (const float*)IN(22);
    const float* ffn_w2     = (const float*)IN(23);
    const float* ffn_b2     = (const float*)IN(24);
    const float* se3_uw     = (const float*)IN(25);
    const float* se3_ub     = (const float*)IN(26);
    const float* se3_ww     = (const float*)IN(27);
    const float* se3_wb     = (const float*)IN(28);
    const float* en_w       = (const float*)IN(29);
    const float* en_b       = (const float*)IN(30);
    float* out = (float*)d_out;

    float *hb, *qkvb, *pairb, *splitb;
    __nv_bfloat16 *xh, *xl, *ah, *al, *fh, *fl, *wh, *wl;
    cudaGetSymbolAddress((void**)&hb,     g_h);
    cudaGetSymbolAddress((void**)&qkvb,   g_qkv);
    cudaGetSymbolAddress((void**)&pairb,  g_pair);
    cudaGetSymbolAddress((void**)&splitb, g_split);
    cudaGetSymbolAddress((void**)&xh, g_xh);
    cudaGetSymbolAddress((void**)&xl, g_xl);
    cudaGetSymbolAddress((void**)&ah, g_ah);
    cudaGetSymbolAddress((void**)&al, g_al);
    cudaGetSymbolAddress((void**)&fh, g_fh);
    cudaGetSymbolAddress((void**)&fl, g_fl);
    cudaGetSymbolAddress((void**)&wh, g_wh);
    cudaGetSymbolAddress((void**)&wl, g_wl);

    cudaFuncSetAttribute(gemm_tc_kernel,
                         cudaFuncAttributeMaxDynamicSharedMemorySize, SMEM_DYN);

    // pre-split all weights into bf16 hi/lo (once per call)
    wsplit_kernel<<<(11796480/4 + 255)/256, 256>>>(qkv_w,  wh + QKVB, wl + QKVB, 11796480/4);
    wsplit_kernel<<<( 3932160/4 + 255)/256, 256>>>(out_w,  wh + OUTB, wl + OUTB,  3932160/4);
    wsplit_kernel<<<(15728640/4 + 255)/256, 256>>>(ffn_w1, wh + F1B,  wl + F1B,  15728640/4);
    wsplit_kernel<<<(15728640/4 + 255)/256, 256>>>(ffn_w2, wh + F2B,  wl + F2B,  15728640/4);

    tab_kernel<<<(TABN + 256)/256, 256>>>(gmu, gsigma, pl_w, pl_b);
    emb_kernel<<<(Mc*Dc + 255)/256, 256>>>(atom_types, atom_emb, hb);
    pair_kernel<<<(Bc*Nc*Nc)/256, 256>>>(coords, pair_types, pair_a, pair_b, pairb);

    for (int l = 0; l < Lc; l++) {
        const float* qb  = qkv_b + l*3*Dc;
        const float* pwp = pp_w + l*Hc;
        const float* pbp = pp_b + l*Hc;
        const float* ob  = out_b + l*Dc;
        const float* l2g = ln2_g + l*Dc;
        const float* l2b = ln2_b + l*Dc;
        const float* b1  = ffn_b1 + l*Fc;
        const float* b2  = ffn_b2 + l*Dc;
        const __nv_bfloat16* qwh = wh + QKVB + (size_t)l*786432;
        const __nv_bfloat16* qwl = wl + QKVB + (size_t)l*786432;
        const __nv_bfloat16* owh = wh + OUTB + (size_t)l*262144;
        const __nv_bfloat16* owl = wl + OUTB + (size_t)l*262144;
        const __nv_bfloat16* w1h = wh + F1B  + (size_t)l*1048576;
        const __nv_bfloat16* w1l = wl + F1B  + (size_t)l*1048576;
        const __nv_bfloat16* w2h = wh + F2B  + (size_t)l*1048576;
        const __nv_bfloat16* w2l = wl + F2B  + (size_t)l*1048576;

        if (l == 0)
            ln_kernel<<<Mc, 128>>>(hb, ln1_g, ln1_b, xh, xl);
        gemm_tc_kernel<<<dim3((3*Dc)/BN, Mc/BM, 1), 256, SMEM_DYN>>>(
            xh, xl, qwh, qwl, nullptr, qkvb, nullptr, nullptr, Mc, 3*Dc, Dc, 0);
        attn_kernel<<<dim3(Bc*Hc, 4), 256>>>(qkvb, qb, pairb, pwp, pbp, ah, al);
        gemm_tc_kernel<<<dim3(Dc/BN, Mc/BM, SPLITK), 256, SMEM_DYN>>>(
            ah, al, owh, owl, nullptr, splitb, nullptr, nullptr, Mc, Dc, Dc, 0);
        reduce_ln_kernel<<<Mc, 128>>>(splitb, ob, hb, l2g, l2b, xh, xl);
        gemm_tc_kernel<<<dim3(Fc/BN, Mc/BM, 1), 256, SMEM_DYN>>>(
            xh, xl, w1h, w1l, b1, nullptr, fh, fl, Mc, Fc, Dc, 1);
        gemm_tc_kernel<<<dim3(Dc/BN, Mc/BM, SPLITK), 256, SMEM_DYN>>>(
            fh, fl, w2h, w2l, nullptr, splitb, nullptr, nullptr, Mc, Dc, Fc, 0);
        if (l < Lc-1) {
            reduce_ln_kernel<<<Mc, 128>>>(splitb, b2, hb,
                                          ln1_g + (l+1)*Dc, ln1_b + (l+1)*Dc, xh, xl);
        } else {
            reduce_splitk<<<(Mc*Dc/4 + 255)/256, 256>>>(splitb, b2, hb, Mc*Dc, Dc);
        }
    }

    coords_kernel<<<(Bc*Nc)/4, 128>>>(coords, pairb, se3_uw, se3_ub, se3_ww, se3_wb, out);
    energy_kernel<<<Bc, 128>>>(hb, en_w, en_b, out);
    (void)in_sizes; (void)out_size;
}